// round 2
// baseline (speedup 1.0000x reference)
#include <cuda_runtime.h>
#include <math.h>

// Scratch (no allocation allowed): preprocessed samples and points.
// samples: (xx, xy, -gamma2*(xx^2+xy^2), 0) per (b,n)
// points:  (2*gamma2*px, 2*gamma2*py, -gamma2*(px^2+py^2), 0) per m
__device__ float4 g_samples[128 * 2048];
__device__ float4 g_points[512];

__global__ void kde_prep_kernel(const float* __restrict__ inputs,
                                const float* __restrict__ pts,
                                int BN, int M, float gamma2) {
    int i = blockIdx.x * blockDim.x + threadIdx.x;
    if (i < BN) {
        float xx = inputs[2 * i];
        float xy = inputs[2 * i + 1];
        g_samples[i] = make_float4(xx, xy, -gamma2 * (xx * xx + xy * xy), 0.0f);
    }
    if (i < M) {
        float px = pts[2 * i];
        float py = pts[2 * i + 1];
        g_points[i] = make_float4(2.0f * gamma2 * px, 2.0f * gamma2 * py,
                                  -gamma2 * (px * px + py * py), 0.0f);
    }
}

// Main kernel: blockIdx.y = batch b, blockIdx.x = m-tile of 128.
// Each thread owns one m, accumulates over all N samples of its b.
// arg2 = am2 + sn + qx*xx + qy*xy   (already in log2 units, incl. -gamma)
// out[b,m] = scale_out * sum_n ex2(arg2)
__global__ __launch_bounds__(128)
void kde_main_kernel(float* __restrict__ out, int N, int M, float scale_out) {
    const int b = blockIdx.y;
    const int m = blockIdx.x * 128 + threadIdx.x;

    const float4 p = g_points[m];
    const float qx = p.x, qy = p.y, am2 = p.z;

    const float4* __restrict__ samp = g_samples + (size_t)b * N;

    __shared__ float4 sh[512];

    float acc0 = 0.0f, acc1 = 0.0f;

    for (int n0 = 0; n0 < N; n0 += 512) {
        // cooperative staged load: 128 threads x 4 float4 (coalesced LDG.128)
        #pragma unroll
        for (int j = 0; j < 4; j++) {
            sh[threadIdx.x + j * 128] = samp[n0 + threadIdx.x + j * 128];
        }
        __syncthreads();

        #pragma unroll 8
        for (int n = 0; n < 512; n += 2) {
            float4 s0 = sh[n];
            float4 s1 = sh[n + 1];

            float t0 = fmaf(qx, s0.x, am2);
            t0 = fmaf(qy, s0.y, t0);
            t0 += s0.z;

            float t1 = fmaf(qx, s1.x, am2);
            t1 = fmaf(qy, s1.y, t1);
            t1 += s1.z;

            float e0, e1;
            asm("ex2.approx.ftz.f32 %0, %1;" : "=f"(e0) : "f"(t0));
            asm("ex2.approx.ftz.f32 %0, %1;" : "=f"(e1) : "f"(t1));

            acc0 += e0;
            acc1 += e1;
        }
        __syncthreads();
    }

    out[(size_t)b * M + m] = (acc0 + acc1) * scale_out;
}

extern "C" void kernel_launch(void* const* d_in, const int* in_sizes, int n_in,
                              void* d_out, int out_size) {
    const float* inputs = (const float*)d_in[0];   // (B, N, d) float32
    const float* pts    = (const float*)d_in[1];   // (M, d) float32
    float* out          = (float*)d_out;           // (B, M) float32

    const int d = 2;
    const int M  = in_sizes[1] / d;                // 512
    const int BN = in_sizes[0] / d;                // B*N = 262144
    const int B  = out_size / M;                   // 128
    const int N  = BN / B;                         // 2048

    // Silverman bandwidth (d=2): h = (4/(d+2))^(1/(d+4)) * N^(-1/(d+4))
    double h = pow(4.0 / (d + 2), 1.0 / (d + 4)) * pow((double)N, -1.0 / (d + 4));
    double coef = 1.0 / pow(2.0 * M_PI * h * h, d / 2.0);
    double gamma = 0.5 / (h * h);
    // fold 1/ln(2) so we can use ex2 directly
    float gamma2 = (float)(gamma * 1.4426950408889634);
    float scale_out = (float)(coef / (double)N);

    {
        int threads = 256;
        int blocks = (BN + threads - 1) / threads;
        kde_prep_kernel<<<blocks, threads>>>(inputs, pts, BN, M, gamma2);
    }
    {
        dim3 grid(M / 128, B);   // (4, 128) = 512 blocks
        kde_main_kernel<<<grid, 128>>>(out, N, M, scale_out);
    }
}

// round 3
// speedup vs baseline: 1.3575x; 1.3575x over previous
#include <cuda_runtime.h>
#include <math.h>

typedef unsigned long long u64;

// Pair-packed SoA scratch (no allocation allowed).
__device__ float g_sxx[128 * 2048];
__device__ float g_sxy[128 * 2048];
__device__ float g_ssn[128 * 2048];
__device__ float g_qx[512];
__device__ float g_qy[512];
__device__ float g_am2[512];

__device__ __forceinline__ u64 pk2(float lo, float hi) {
    u64 r; asm("mov.b64 %0, {%1, %2};" : "=l"(r) : "f"(lo), "f"(hi)); return r;
}
__device__ __forceinline__ void upk2(u64 v, float& lo, float& hi) {
    asm("mov.b64 {%0, %1}, %2;" : "=f"(lo), "=f"(hi) : "l"(v));
}
__device__ __forceinline__ u64 fma2(u64 a, u64 b, u64 c) {
    u64 d; asm("fma.rn.f32x2 %0, %1, %2, %3;" : "=l"(d) : "l"(a), "l"(b), "l"(c)); return d;
}
__device__ __forceinline__ u64 add2(u64 a, u64 b) {
    u64 d; asm("add.rn.f32x2 %0, %1, %2;" : "=l"(d) : "l"(a), "l"(b)); return d;
}
__device__ __forceinline__ float ex2f(float x) {
    float e; asm("ex2.approx.ftz.f32 %0, %1;" : "=f"(e) : "f"(x)); return e;
}

__global__ void kde_prep_kernel(const float* __restrict__ inputs,
                                const float* __restrict__ pts,
                                int BN, int M, float gamma2) {
    int i = blockIdx.x * blockDim.x + threadIdx.x;
    if (i < BN) {
        float xx = inputs[2 * i];
        float xy = inputs[2 * i + 1];
        g_sxx[i] = xx;
        g_sxy[i] = xy;
        g_ssn[i] = -gamma2 * (xx * xx + xy * xy);
    }
    if (i < M) {
        float px = pts[2 * i];
        float py = pts[2 * i + 1];
        g_qx[i]  = 2.0f * gamma2 * px;
        g_qy[i]  = 2.0f * gamma2 * py;
        g_am2[i] = -gamma2 * (px * px + py * py);
    }
}

// grid = (M/64, B), block = 64 threads. Each thread owns one m for batch b.
// arg(n) = am2 + qx*xx[n] + qy*xy[n] + sn[n]  (log2 units); out = scale * sum ex2(arg)
__global__ __launch_bounds__(64)
void kde_main_kernel(float* __restrict__ out, int N, int M, float scale_out) {
    const int b = blockIdx.y;
    const int m = blockIdx.x * 64 + threadIdx.x;

    __shared__ float sxx[2048];
    __shared__ float sxy[2048];
    __shared__ float ssn[2048];

    // Stage the whole batch's samples once (float4 = 4 samples per LDG/STS).
    {
        const float4* gx = (const float4*)(g_sxx + (size_t)b * N);
        const float4* gy = (const float4*)(g_sxy + (size_t)b * N);
        const float4* gs = (const float4*)(g_ssn + (size_t)b * N);
        float4* hx = (float4*)sxx;
        float4* hy = (float4*)sxy;
        float4* hs = (float4*)ssn;
        const int nv = N >> 2;   // 512 float4 per array
        for (int j = threadIdx.x; j < nv; j += 64) {
            hx[j] = gx[j];
            hy[j] = gy[j];
            hs[j] = gs[j];
        }
    }
    __syncthreads();

    const float qx  = g_qx[m];
    const float qy  = g_qy[m];
    const float am2 = g_am2[m];
    const u64 qx2  = pk2(qx, qx);
    const u64 qy2  = pk2(qy, qy);
    const u64 am22 = pk2(am2, am2);

    u64 acc01 = 0ull;  // (+0.0f, +0.0f)
    u64 acc23 = 0ull;

    const float4* hx = (const float4*)sxx;
    const float4* hy = (const float4*)sxy;
    const float4* hs = (const float4*)ssn;

    const int nv = N >> 2;
    #pragma unroll 4
    for (int j = 0; j < nv; j++) {
        float4 X = hx[j];
        float4 Y = hy[j];
        float4 S = hs[j];

        u64 t01 = fma2(qx2, pk2(X.x, X.y), am22);
        t01 = fma2(qy2, pk2(Y.x, Y.y), t01);
        t01 = add2(t01, pk2(S.x, S.y));

        u64 t23 = fma2(qx2, pk2(X.z, X.w), am22);
        t23 = fma2(qy2, pk2(Y.z, Y.w), t23);
        t23 = add2(t23, pk2(S.z, S.w));

        float t0, t1, t2, t3;
        upk2(t01, t0, t1);
        upk2(t23, t2, t3);

        float e0 = ex2f(t0);
        float e1 = ex2f(t1);
        float e2 = ex2f(t2);
        float e3 = ex2f(t3);

        acc01 = add2(acc01, pk2(e0, e1));
        acc23 = add2(acc23, pk2(e2, e3));
    }

    float a0, a1, a2, a3;
    upk2(acc01, a0, a1);
    upk2(acc23, a2, a3);
    out[(size_t)b * M + m] = ((a0 + a1) + (a2 + a3)) * scale_out;
}

extern "C" void kernel_launch(void* const* d_in, const int* in_sizes, int n_in,
                              void* d_out, int out_size) {
    const float* inputs = (const float*)d_in[0];   // (B, N, 2) float32
    const float* pts    = (const float*)d_in[1];   // (M, 2) float32
    float* out          = (float*)d_out;           // (B, M) float32

    const int d = 2;
    const int M  = in_sizes[1] / d;                // 512
    const int BN = in_sizes[0] / d;                // B*N
    const int B  = out_size / M;                   // 128
    const int N  = BN / B;                         // 2048

    // Silverman bandwidth (d=2)
    double h = pow(4.0 / (d + 2), 1.0 / (d + 4)) * pow((double)N, -1.0 / (d + 4));
    double coef = 1.0 / pow(2.0 * M_PI * h * h, d / 2.0);
    double gamma = 0.5 / (h * h);
    float gamma2 = (float)(gamma * 1.4426950408889634);  // fold 1/ln2 for ex2
    float scale_out = (float)(coef / (double)N);

    {
        int threads = 256;
        int blocks = (BN + threads - 1) / threads;
        kde_prep_kernel<<<blocks, threads>>>(inputs, pts, BN, M, gamma2);
    }
    {
        dim3 grid(M / 64, B);   // (8, 128) = 1024 blocks, 64 threads each
        kde_main_kernel<<<grid, 64>>>(out, N, M, scale_out);
    }
}